// round 1
// baseline (speedup 1.0000x reference)
#include <cuda_runtime.h>
#include <cuda_bf16.h>

// Problem: cummax along axis=2 of x[B=8, Tt=128, Ts=128, C=512] fp32.
// out[b,t,j,c] = max_{j'<=j} x[b,t,j',c]
//
// Mapping: one thread per (b,t, 4-channel group). Thread walks j=0..127
// with a float4 running max in registers. Coalesced float4 loads/stores,
// j-stride = 512 floats = 2KB. Pure streaming, HBM-bound.

static __device__ __forceinline__ float4 f4max(float4 a, float4 b) {
    float4 r;
    r.x = fmaxf(a.x, b.x);
    r.y = fmaxf(a.y, b.y);
    r.z = fmaxf(a.z, b.z);
    r.w = fmaxf(a.w, b.w);
    return r;
}

// B*Tt = 1024 rows, each row is [Ts=128, C=512].
// C/4 = 128 float4 per j. Columns total = 1024 * 128 = 131072 threads.
__global__ void __launch_bounds__(256, 8) cummax_kernel(
    const float4* __restrict__ in, float4* __restrict__ out)
{
    constexpr int TS = 128;
    constexpr int C4 = 128;               // 512 channels / 4
    const int col = blockIdx.x * blockDim.x + threadIdx.x;  // 0..131071
    const int bt  = col >> 7;             // which (b,t) row
    const int c4  = col & 127;            // which float4 within C

    const float4* __restrict__ p = in  + (size_t)bt * TS * C4 + c4;
    float4* __restrict__       q = out + (size_t)bt * TS * C4 + c4;

    float4 m = p[0];
    q[0] = m;

    // Unroll to expose independent loads (MLP) ahead of the serial max chain.
    #pragma unroll 8
    for (int j = 1; j < TS; ++j) {
        float4 v = p[(size_t)j * C4];
        m = f4max(m, v);
        q[(size_t)j * C4] = m;
    }
}

extern "C" void kernel_launch(void* const* d_in, const int* in_sizes, int n_in,
                              void* d_out, int out_size)
{
    const float4* x = (const float4*)d_in[0];
    float4* y = (float4*)d_out;

    // total float4 columns = 8*128 * (512/4) = 131072
    const int threads = 256;
    const int total_cols = 8 * 128 * (512 / 4);
    const int blocks = total_cols / threads;  // 512
    cummax_kernel<<<blocks, threads>>>(x, y);
}